// round 1
// baseline (speedup 1.0000x reference)
#include <cuda_runtime.h>
#include <math.h>

// Problem constants (fixed dataset)
#define NQ     4096
#define NM     100000
#define D      128
#define KTOP   3
#define NCHUNK 37
#define CHUNK  2703     // ceil(NM / NCHUNK)
#define QTILE  128
#define MTILE  128
#define PITCH  132      // smem row pitch in floats (16B-aligned rows, reduced conflicts)

#define SMEM_BYTES (2 * QTILE * PITCH * 4)

// Scratch (device globals -- no allocation allowed)
__device__ float g_qn[NQ * D];
__device__ float g_invm[NM];
__device__ float g_cval[NQ * NCHUNK * KTOP];
__device__ int   g_cidx[NQ * NCHUNK * KTOP];

// ---------------------------------------------------------------------------
// insert (s, gi) into descending top-3 (v0>=v1>=v2), tie -> lower index wins
// ---------------------------------------------------------------------------
__device__ __forceinline__ void ins_tb(float s, int gi,
                                       float& v0, int& i0,
                                       float& v1, int& i1,
                                       float& v2, int& i2) {
    bool b2 = (s > v2) || (s == v2 && gi < i2);
    if (b2) {
        bool b1 = (s > v1) || (s == v1 && gi < i1);
        if (b1) {
            bool b0 = (s > v0) || (s == v0 && gi < i0);
            if (b0) { v2 = v1; i2 = i1; v1 = v0; i1 = i0; v0 = s; i0 = gi; }
            else    { v2 = v1; i2 = i1; v1 = s;  i1 = gi; }
        } else      { v2 = s;  i2 = gi; }
    }
}

// ---------------------------------------------------------------------------
// Pre-pass: normalize queries (one warp per row)
// ---------------------------------------------------------------------------
__global__ void norm_q_kernel(const float* __restrict__ q) {
    int warp = (blockIdx.x * blockDim.x + threadIdx.x) >> 5;
    int lane = threadIdx.x & 31;
    if (warp >= NQ) return;
    float4 v = *(const float4*)(q + (size_t)warp * D + lane * 4);
    float ss = v.x * v.x + v.y * v.y + v.z * v.z + v.w * v.w;
    #pragma unroll
    for (int o = 16; o; o >>= 1) ss += __shfl_xor_sync(0xffffffffu, ss, o);
    float inv = 1.0f / fmaxf(sqrtf(ss), 1e-12f);
    float4 r = { v.x * inv, v.y * inv, v.z * inv, v.w * inv };
    *(float4*)(g_qn + (size_t)warp * D + lane * 4) = r;
}

// ---------------------------------------------------------------------------
// Pre-pass: 1/||m_row|| (one warp per row)
// ---------------------------------------------------------------------------
__global__ void norm_m_kernel(const float* __restrict__ m) {
    int warp = (blockIdx.x * blockDim.x + threadIdx.x) >> 5;
    int lane = threadIdx.x & 31;
    if (warp >= NM) return;
    float4 v = *(const float4*)(m + (size_t)warp * D + lane * 4);
    float ss = v.x * v.x + v.y * v.y + v.z * v.z + v.w * v.w;
    #pragma unroll
    for (int o = 16; o; o >>= 1) ss += __shfl_xor_sync(0xffffffffu, ss, o);
    if (lane == 0) g_invm[warp] = 1.0f / fmaxf(sqrtf(ss), 1e-12f);
}

// ---------------------------------------------------------------------------
// Main: tiled fp32 GEMM (cosine sims) fused with streaming per-query top-3.
// Block = 256 threads (16x16), 8x8 microtile. Grid = (NQ/128, NCHUNK).
// ---------------------------------------------------------------------------
__global__ __launch_bounds__(256) void topk_kernel(const float* __restrict__ mem) {
    extern __shared__ float sh[];
    float* qs = sh;                     // [128][PITCH]  (normalized queries)
    float* ms = sh + QTILE * PITCH;     // [128][PITCH]  (normalized memory tile)

    int t  = threadIdx.x;
    int tx = t & 15;          // memory direction
    int ty = t >> 4;          // query direction
    int qbase  = blockIdx.x * QTILE;
    int mstart = blockIdx.y * CHUNK;
    int mend   = min(mstart + CHUNK, NM);

    // Load query tile once (coalesced, conflict-free)
    for (int i = t; i < QTILE * 32; i += 256) {
        int row = i >> 5, c4 = (i & 31) * 4;
        *(float4*)(qs + row * PITCH + c4) =
            *(const float4*)(g_qn + (size_t)(qbase + row) * D + c4);
    }

    // Per-thread top-3 for 8 query rows (query local = ty + 16*r)
    float tv0[8], tv1[8], tv2[8];
    int   ti0[8], ti1[8], ti2[8];
    #pragma unroll
    for (int r = 0; r < 8; r++) {
        tv0[r] = tv1[r] = tv2[r] = -2.0f;
        ti0[r] = ti1[r] = ti2[r] = 0x7fffffff;
    }

    int ntiles = (mend - mstart + MTILE - 1) / MTILE;
    for (int tile = 0; tile < ntiles; tile++) {
        int tb = mstart + tile * MTILE;

        __syncthreads();
        // Load + normalize memory tile (coalesced)
        for (int i = t; i < MTILE * 32; i += 256) {
            int row = i >> 5, c4 = (i & 31) * 4;
            int gr = min(tb + row, NM - 1);
            float inv = g_invm[gr];
            float4 v = *(const float4*)(mem + (size_t)gr * D + c4);
            v.x *= inv; v.y *= inv; v.z *= inv; v.w *= inv;
            *(float4*)(ms + row * PITCH + c4) = v;
        }
        __syncthreads();

        // 128x128 sim tile via register blocking
        float acc[8][8];
        #pragma unroll
        for (int r = 0; r < 8; r++)
            #pragma unroll
            for (int c = 0; c < 8; c++) acc[r][c] = 0.0f;

        const float* qp = qs + ty * PITCH;
        const float* mp = ms + tx * PITCH;
        #pragma unroll 1
        for (int kk = 0; kk < D; kk += 4) {
            float4 a[8], b[8];
            #pragma unroll
            for (int r = 0; r < 8; r++)
                a[r] = *(const float4*)(qp + r * 16 * PITCH + kk);
            #pragma unroll
            for (int c = 0; c < 8; c++)
                b[c] = *(const float4*)(mp + c * 16 * PITCH + kk);
            #pragma unroll
            for (int r = 0; r < 8; r++)
                #pragma unroll
                for (int c = 0; c < 8; c++) {
                    acc[r][c] = fmaf(a[r].x, b[c].x, acc[r][c]);
                    acc[r][c] = fmaf(a[r].y, b[c].y, acc[r][c]);
                    acc[r][c] = fmaf(a[r].z, b[c].z, acc[r][c]);
                    acc[r][c] = fmaf(a[r].w, b[c].w, acc[r][c]);
                }
        }

        // Streaming top-3 update. gi ascending within a thread, so strict '>'
        // keeps the earliest (lowest) index on exact ties.
        #pragma unroll
        for (int c = 0; c < 8; c++) {
            int gi = tb + tx + 16 * c;
            bool ok = gi < mend;
            #pragma unroll
            for (int r = 0; r < 8; r++) {
                float s = acc[r][c];
                if (ok && s > tv2[r]) {
                    if (s > tv1[r]) {
                        if (s > tv0[r]) {
                            tv2[r] = tv1[r]; ti2[r] = ti1[r];
                            tv1[r] = tv0[r]; ti1[r] = ti0[r];
                            tv0[r] = s;      ti0[r] = gi;
                        } else {
                            tv2[r] = tv1[r]; ti2[r] = ti1[r];
                            tv1[r] = s;      ti1[r] = gi;
                        }
                    } else { tv2[r] = s; ti2[r] = gi; }
                }
            }
        }
    }

    // Reduce across the 16 threads (same ty) sharing each query row.
    // XOR offsets 8,4,2,1 stay within the 16-lane half-warp group.
    #pragma unroll
    for (int off = 8; off; off >>= 1) {
        #pragma unroll
        for (int r = 0; r < 8; r++) {
            float ov0 = __shfl_xor_sync(0xffffffffu, tv0[r], off);
            int   oi0 = __shfl_xor_sync(0xffffffffu, ti0[r], off);
            float ov1 = __shfl_xor_sync(0xffffffffu, tv1[r], off);
            int   oi1 = __shfl_xor_sync(0xffffffffu, ti1[r], off);
            float ov2 = __shfl_xor_sync(0xffffffffu, tv2[r], off);
            int   oi2 = __shfl_xor_sync(0xffffffffu, ti2[r], off);
            ins_tb(ov0, oi0, tv0[r], ti0[r], tv1[r], ti1[r], tv2[r], ti2[r]);
            ins_tb(ov1, oi1, tv0[r], ti0[r], tv1[r], ti1[r], tv2[r], ti2[r]);
            ins_tb(ov2, oi2, tv0[r], ti0[r], tv1[r], ti1[r], tv2[r], ti2[r]);
        }
    }

    if (tx == 0) {
        #pragma unroll
        for (int r = 0; r < 8; r++) {
            int q = qbase + ty + 16 * r;
            size_t base = ((size_t)q * NCHUNK + blockIdx.y) * KTOP;
            g_cval[base + 0] = tv0[r]; g_cidx[base + 0] = ti0[r];
            g_cval[base + 1] = tv1[r]; g_cidx[base + 1] = ti1[r];
            g_cval[base + 2] = tv2[r]; g_cidx[base + 2] = ti2[r];
        }
    }
}

// ---------------------------------------------------------------------------
// Merge NCHUNK*3 candidates per query -> final top-3 (warp per query).
// Output: [distances NQ*3 | indices-as-float NQ*3]
// ---------------------------------------------------------------------------
__global__ void merge_kernel(float* __restrict__ out) {
    int warp = (blockIdx.x * blockDim.x + threadIdx.x) >> 5;
    int lane = threadIdx.x & 31;
    if (warp >= NQ) return;

    float v0 = -2.0f, v1 = -2.0f, v2 = -2.0f;
    int   i0 = 0x7fffffff, i1 = 0x7fffffff, i2 = 0x7fffffff;

    size_t base = (size_t)warp * NCHUNK * KTOP;
    for (int i = lane; i < NCHUNK * KTOP; i += 32) {
        float s = g_cval[base + i];
        int  gi = g_cidx[base + i];
        ins_tb(s, gi, v0, i0, v1, i1, v2, i2);
    }
    #pragma unroll
    for (int off = 16; off; off >>= 1) {
        float ov0 = __shfl_xor_sync(0xffffffffu, v0, off);
        int   oi0 = __shfl_xor_sync(0xffffffffu, i0, off);
        float ov1 = __shfl_xor_sync(0xffffffffu, v1, off);
        int   oi1 = __shfl_xor_sync(0xffffffffu, i1, off);
        float ov2 = __shfl_xor_sync(0xffffffffu, v2, off);
        int   oi2 = __shfl_xor_sync(0xffffffffu, i2, off);
        ins_tb(ov0, oi0, v0, i0, v1, i1, v2, i2);
        ins_tb(ov1, oi1, v0, i0, v1, i1, v2, i2);
        ins_tb(ov2, oi2, v0, i0, v1, i1, v2, i2);
    }
    if (lane == 0) {
        out[(size_t)warp * 3 + 0] = 1.0f - v0;
        out[(size_t)warp * 3 + 1] = 1.0f - v1;
        out[(size_t)warp * 3 + 2] = 1.0f - v2;
        out[(size_t)NQ * 3 + (size_t)warp * 3 + 0] = (float)i0;
        out[(size_t)NQ * 3 + (size_t)warp * 3 + 1] = (float)i1;
        out[(size_t)NQ * 3 + (size_t)warp * 3 + 2] = (float)i2;
    }
}

// ---------------------------------------------------------------------------
extern "C" void kernel_launch(void* const* d_in, const int* in_sizes, int n_in,
                              void* d_out, int out_size) {
    const float* q   = (const float*)d_in[0];   // [4096, 128] f32
    const float* mem = (const float*)d_in[1];   // [100000, 128] f32
    float* out = (float*)d_out;

    cudaFuncSetAttribute(topk_kernel,
                         cudaFuncAttributeMaxDynamicSharedMemorySize, SMEM_BYTES);

    norm_q_kernel<<<(NQ * 32) / 256, 256>>>(q);
    norm_m_kernel<<<(NM * 32 + 255) / 256, 256>>>(mem);

    dim3 grid(NQ / QTILE, NCHUNK);
    topk_kernel<<<grid, 256, SMEM_BYTES>>>(mem);

    merge_kernel<<<(NQ * 32) / 256, 256>>>(out);
}

// round 3
// speedup vs baseline: 2.6836x; 2.6836x over previous
#include <cuda_runtime.h>
#include <cuda_bf16.h>
#include <cstdint>
#include <math.h>

// ---------------- problem constants ----------------
#define NQ     4096
#define NM     100000
#define D      128
#define NCH    37
#define CHUNK  2703          // ceil(NM / NCH)
#define QT     128           // queries per CTA (block M)
#define NT     128           // memory rows per tile (block N)
#define KC     4             // candidates kept per (query, chunk)

#define A_BYTES   (QT * D * 2)          // 32768
#define B_BYTES   (NT * D * 2)          // 32768
#define SMEM_DYN  (A_BYTES + 2 * B_BYTES + 1024)

// ---------------- device scratch ----------------
__device__ float          g_qn[NQ * D];       // normalized queries (fp32)
__device__ __nv_bfloat16  g_qbf[NQ * D];      // normalized queries (bf16)
__device__ __nv_bfloat16  g_mbf[NM * D];      // normalized memory (bf16)
__device__ float          g_invm[NM];         // 1/||m||
__device__ float          g_cv[NQ * NCH * KC];
__device__ int            g_ci[NQ * NCH * KC];

// ---------------- PTX helpers (family-generic only: sm_80-era) ----------------
__device__ __forceinline__ uint32_t s2u(const void* p) {
    uint32_t a;
    asm("{ .reg .u64 t; cvta.to.shared.u64 t, %1; cvt.u32.u64 %0, t; }"
        : "=r"(a) : "l"(p));
    return a;
}

__device__ __forceinline__ void cp16(uint32_t dst, const void* src) {
    asm volatile("cp.async.cg.shared.global [%0], [%1], 16;" :: "r"(dst), "l"(src));
}
#define CP_COMMIT() asm volatile("cp.async.commit_group;" ::: "memory")
#define CP_WAIT0()  asm volatile("cp.async.wait_group 0;" ::: "memory")

__device__ __forceinline__ void ldsm_x4(uint32_t addr, uint32_t& r0, uint32_t& r1,
                                        uint32_t& r2, uint32_t& r3) {
    asm volatile("ldmatrix.sync.aligned.m8n8.x4.shared.b16 {%0,%1,%2,%3}, [%4];"
        : "=r"(r0), "=r"(r1), "=r"(r2), "=r"(r3) : "r"(addr));
}

__device__ __forceinline__ void mma16816(float* d, const uint32_t* a, const uint32_t* b) {
    asm volatile("mma.sync.aligned.m16n8k16.row.col.f32.bf16.bf16.f32 "
        "{%0,%1,%2,%3}, {%4,%5,%6,%7}, {%8,%9}, {%0,%1,%2,%3};"
        : "+f"(d[0]), "+f"(d[1]), "+f"(d[2]), "+f"(d[3])
        : "r"(a[0]), "r"(a[1]), "r"(a[2]), "r"(a[3]), "r"(b[0]), "r"(b[1]));
}

// swizzled byte offset: row-major [row][128 bf16], 16B chunks XOR-permuted per row
__device__ __forceinline__ uint32_t sw_off(int row, int c16) {
    return (uint32_t)row * 256u + (uint32_t)((c16 ^ (row & 7)) * 16);
}

// ---------------- top-k inserts ----------------
__device__ __forceinline__ void ins_tb4(float s, int gi,
    float& v0, int& i0, float& v1, int& i1, float& v2, int& i2, float& v3, int& i3) {
    bool b3 = (s > v3) || (s == v3 && gi < i3);
    if (!b3) return;
    bool b1 = (s > v1) || (s == v1 && gi < i1);
    if (b1) {
        bool b0 = (s > v0) || (s == v0 && gi < i0);
        if (b0) { v3=v2;i3=i2; v2=v1;i2=i1; v1=v0;i1=i0; v0=s;i0=gi; }
        else    { v3=v2;i3=i2; v2=v1;i2=i1; v1=s;i1=gi; }
    } else {
        bool b2 = (s > v2) || (s == v2 && gi < i2);
        if (b2) { v3=v2;i3=i2; v2=s;i2=gi; }
        else    { v3=s; i3=gi; }
    }
}

__device__ __forceinline__ void ins_tb3(float s, int gi,
    float& v0, int& i0, float& v1, int& i1, float& v2, int& i2) {
    bool b2 = (s > v2) || (s == v2 && gi < i2);
    if (!b2) return;
    bool b1 = (s > v1) || (s == v1 && gi < i1);
    if (b1) {
        bool b0 = (s > v0) || (s == v0 && gi < i0);
        if (b0) { v2=v1;i2=i1; v1=v0;i1=i0; v0=s;i0=gi; }
        else    { v2=v1;i2=i1; v1=s;i1=gi; }
    } else      { v2=s; i2=gi; }
}

// ---------------- prep kernels ----------------
__global__ void norm_q_kernel(const float* __restrict__ q) {
    int warp = (blockIdx.x * blockDim.x + threadIdx.x) >> 5;
    int lane = threadIdx.x & 31;
    if (warp >= NQ) return;
    float4 v = *(const float4*)(q + (size_t)warp * D + lane * 4);
    float ss = v.x*v.x + v.y*v.y + v.z*v.z + v.w*v.w;
    #pragma unroll
    for (int o = 16; o; o >>= 1) ss += __shfl_xor_sync(0xffffffffu, ss, o);
    float inv = 1.0f / fmaxf(sqrtf(ss), 1e-12f);
    float4 r = { v.x*inv, v.y*inv, v.z*inv, v.w*inv };
    *(float4*)(g_qn + (size_t)warp * D + lane * 4) = r;
    __nv_bfloat162 p0 = __floats2bfloat162_rn(r.x, r.y);
    __nv_bfloat162 p1 = __floats2bfloat162_rn(r.z, r.w);
    *(__nv_bfloat162*)(g_qbf + (size_t)warp * D + lane * 4)     = p0;
    *(__nv_bfloat162*)(g_qbf + (size_t)warp * D + lane * 4 + 2) = p1;
}

__global__ void norm_m_kernel(const float* __restrict__ m) {
    int warp = (blockIdx.x * blockDim.x + threadIdx.x) >> 5;
    int lane = threadIdx.x & 31;
    if (warp >= NM) return;
    float4 v = *(const float4*)(m + (size_t)warp * D + lane * 4);
    float ss = v.x*v.x + v.y*v.y + v.z*v.z + v.w*v.w;
    #pragma unroll
    for (int o = 16; o; o >>= 1) ss += __shfl_xor_sync(0xffffffffu, ss, o);
    float inv = 1.0f / fmaxf(sqrtf(ss), 1e-12f);
    if (lane == 0) g_invm[warp] = inv;
    __nv_bfloat162 p0 = __floats2bfloat162_rn(v.x*inv, v.y*inv);
    __nv_bfloat162 p1 = __floats2bfloat162_rn(v.z*inv, v.w*inv);
    *(__nv_bfloat162*)(g_mbf + (size_t)warp * D + lane * 4)     = p0;
    *(__nv_bfloat162*)(g_mbf + (size_t)warp * D + lane * 4 + 2) = p1;
}

// ---------------- main HMMA + top-4 kernel ----------------
// 256 threads = 8 warps laid out 4(M) x 2(N). Block tile 128x128, K=128.
__global__ __launch_bounds__(256) void mma_topk_kernel() {
    extern __shared__ __align__(16) uint8_t dyn[];

    int tid  = threadIdx.x;
    int wid  = tid >> 5;
    int lane = tid & 31;
    int wm   = wid & 3;       // warp row: 32 queries
    int wn   = wid >> 2;      // warp col: 64 memory rows

    // align dynamic smem to 1024
    uint32_t raw  = s2u(dyn);
    uint32_t base = (raw + 1023u) & ~1023u;
    uint32_t aSm  = base;
    uint32_t bSm  = base + A_BYTES;

    int qbase  = blockIdx.x * QT;
    int chunk  = blockIdx.y;
    int mstart = chunk * CHUNK;
    int mend   = min(mstart + CHUNK, NM);
    int T      = (mend - mstart + NT - 1) / NT;

    // ---- prologue: A tile + B tile 0 via cp.async ----
    {
        int row = tid >> 1;                 // 128 rows, 2 threads/row
        int c16a = (tid & 1) * 8;
        #pragma unroll
        for (int j = 0; j < 8; ++j) {
            int c16 = c16a + j;
            cp16(aSm + sw_off(row, c16), g_qbf + (size_t)(qbase + row) * D + c16 * 8);
        }
        int gr = min(mstart + row, NM - 1);
        #pragma unroll
        for (int j = 0; j < 8; ++j) {
            int c16 = c16a + j;
            cp16(bSm + sw_off(row, c16), g_mbf + (size_t)gr * D + c16 * 8);
        }
    }
    CP_COMMIT();
    CP_WAIT0();
    __syncthreads();

    // per-thread top-4 for 4 row-slots (rs = mt*2 + half)
    float tv0[4], tv1[4], tv2[4], tv3[4];
    int   ti0[4], ti1[4], ti2[4], ti3[4];
    #pragma unroll
    for (int r = 0; r < 4; ++r) {
        tv0[r]=tv1[r]=tv2[r]=tv3[r] = -2.0f;
        ti0[r]=ti1[r]=ti2[r]=ti3[r] = 0x7fffffff;
    }

    // A ldmatrix row index (constant over tiles)
    int rowA0 = wm * 32 + (lane & 15);
    int hiA   = lane >> 4;                  // k-half select
    // B ldmatrix row pattern
    int grp   = lane >> 3;                  // 0..3
    int rowB0 = wn * 64 + (lane & 7) + (grp >> 1) * 8;
    int hiB   = grp & 1;

    for (int t = 0; t < T; ++t) {
        bool hn = (t + 1 < T);
        // issue next B tile loads
        if (hn) {
            uint32_t bNext = bSm + ((t + 1) & 1) * B_BYTES;
            int row = tid >> 1;
            int c16a = (tid & 1) * 8;
            int gr = min(mstart + (t + 1) * NT + row, NM - 1);
            #pragma unroll
            for (int j = 0; j < 8; ++j) {
                int c16 = c16a + j;
                cp16(bNext + sw_off(row, c16), g_mbf + (size_t)gr * D + c16 * 8);
            }
            CP_COMMIT();
        }

        uint32_t bB = bSm + (t & 1) * B_BYTES;
        int tb = mstart + t * NT;

        // ---- 128x128x128 block tile ----
        float acc[2][8][4];
        #pragma unroll
        for (int mt = 0; mt < 2; ++mt)
            #pragma unroll
            for (int nt = 0; nt < 8; ++nt)
                #pragma unroll
                for (int e = 0; e < 4; ++e) acc[mt][nt][e] = 0.0f;

        #pragma unroll
        for (int kk = 0; kk < 8; ++kk) {
            uint32_t a[2][4];
            #pragma unroll
            for (int mt = 0; mt < 2; ++mt) {
                int row = rowA0 + mt * 16;
                ldsm_x4(aSm + sw_off(row, 2 * kk + hiA),
                        a[mt][0], a[mt][1], a[mt][2], a[mt][3]);
            }
            uint32_t b[8][2];
            #pragma unroll
            for (int j = 0; j < 4; ++j) {
                int row = rowB0 + j * 16;
                ldsm_x4(bB + sw_off(row, 2 * kk + hiB),
                        b[2*j][0], b[2*j][1], b[2*j+1][0], b[2*j+1][1]);
            }
            #pragma unroll
            for (int mt = 0; mt < 2; ++mt)
                #pragma unroll
                for (int nt = 0; nt < 8; ++nt)
                    mma16816(acc[mt][nt], a[mt], b[nt]);
        }

        // ---- streaming top-4 epilogue (gi ascending per row-slot) ----
        #pragma unroll
        for (int mt = 0; mt < 2; ++mt)
            #pragma unroll
            for (int h = 0; h < 2; ++h) {
                const int rs = mt * 2 + h;
                #pragma unroll
                for (int nt = 0; nt < 8; ++nt)
                    #pragma unroll
                    for (int c = 0; c < 2; ++c) {
                        float s = acc[mt][nt][h * 2 + c];
                        int gi = tb + wn * 64 + nt * 8 + (lane & 3) * 2 + c;
                        if (gi < mend && s > tv3[rs]) {
                            if (s > tv1[rs]) {
                                if (s > tv0[rs]) {
                                    tv3[rs]=tv2[rs];ti3[rs]=ti2[rs];
                                    tv2[rs]=tv1[rs];ti2[rs]=ti1[rs];
                                    tv1[rs]=tv0[rs];ti1[rs]=ti0[rs];
                                    tv0[rs]=s;      ti0[rs]=gi;
                                } else {
                                    tv3[rs]=tv2[rs];ti3[rs]=ti2[rs];
                                    tv2[rs]=tv1[rs];ti2[rs]=ti1[rs];
                                    tv1[rs]=s;      ti1[rs]=gi;
                                }
                            } else {
                                if (s > tv2[rs]) {
                                    tv3[rs]=tv2[rs];ti3[rs]=ti2[rs];
                                    tv2[rs]=s;      ti2[rs]=gi;
                                } else { tv3[rs]=s; ti3[rs]=gi; }
                            }
                        }
                    }
            }

        if (hn) CP_WAIT0();
        __syncthreads();
    }

    // ---- merge across the 4 lanes sharing each row (xor 1, 2) ----
    #pragma unroll
    for (int off = 1; off <= 2; off <<= 1) {
        #pragma unroll
        for (int rs = 0; rs < 4; ++rs) {
            float ov0 = __shfl_xor_sync(0xffffffffu, tv0[rs], off);
            int   oi0 = __shfl_xor_sync(0xffffffffu, ti0[rs], off);
            float ov1 = __shfl_xor_sync(0xffffffffu, tv1[rs], off);
            int   oi1 = __shfl_xor_sync(0xffffffffu, ti1[rs], off);
            float ov2 = __shfl_xor_sync(0xffffffffu, tv2[rs], off);
            int   oi2 = __shfl_xor_sync(0xffffffffu, ti2[rs], off);
            float ov3 = __shfl_xor_sync(0xffffffffu, tv3[rs], off);
            int   oi3 = __shfl_xor_sync(0xffffffffu, ti3[rs], off);
            ins_tb4(ov0, oi0, tv0[rs],ti0[rs], tv1[rs],ti1[rs], tv2[rs],ti2[rs], tv3[rs],ti3[rs]);
            ins_tb4(ov1, oi1, tv0[rs],ti0[rs], tv1[rs],ti1[rs], tv2[rs],ti2[rs], tv3[rs],ti3[rs]);
            ins_tb4(ov2, oi2, tv0[rs],ti0[rs], tv1[rs],ti1[rs], tv2[rs],ti2[rs], tv3[rs],ti3[rs]);
            ins_tb4(ov3, oi3, tv0[rs],ti0[rs], tv1[rs],ti1[rs], tv2[rs],ti2[rs], tv3[rs],ti3[rs]);
        }
    }
    __syncthreads();   // smem reuse safe (all cp.async drained)

    // ---- cross-warp_n merge via smem ----
    float* smv = (float*)dyn;                         // [2][128][4]
    int*   smi = (int*)(dyn + 2 * 128 * 4 * 4);       // [2][128][4]
    if ((lane & 3) == 0) {
        #pragma unroll
        for (int rs = 0; rs < 4; ++rs) {
            int row = wm * 32 + (rs >> 1) * 16 + (lane >> 2) + (rs & 1) * 8;
            int o = (wn * 128 + row) * 4;
            smv[o+0]=tv0[rs]; smi[o+0]=ti0[rs];
            smv[o+1]=tv1[rs]; smi[o+1]=ti1[rs];
            smv[o+2]=tv2[rs]; smi[o+2]=ti2[rs];
            smv[o+3]=tv3[rs]; smi[o+3]=ti3[rs];
        }
    }
    __syncthreads();
    if (tid < 128) {
        int row = tid;
        int o0 = row * 4, o1 = (128 + row) * 4;
        float v0 = smv[o0+0], v1 = smv[o0+1], v2 = smv[o0+2], v3 = smv[o0+3];
        int   i0 = smi[o0+0], i1 = smi[o0+1], i2 = smi[o0+2], i3 = smi[o0+3];
        #pragma unroll
        for (int j = 0; j < 4; ++j)
            ins_tb4(smv[o1+j], smi[o1+j], v0,i0, v1,i1, v2,i2, v3,i3);
        size_t cb = ((size_t)(qbase + row) * NCH + chunk) * KC;
        g_cv[cb+0]=v0; g_ci[cb+0]=i0;
        g_cv[cb+1]=v1; g_ci[cb+1]=i1;
        g_cv[cb+2]=v2; g_ci[cb+2]=i2;
        g_cv[cb+3]=v3; g_ci[cb+3]=i3;
    }
}

// ---------------- exact fp32 rescore + final top-3 ----------------
__global__ void rescore_kernel(const float* __restrict__ mem, float* __restrict__ out) {
    int warp = (blockIdx.x * blockDim.x + threadIdx.x) >> 5;
    int lane = threadIdx.x & 31;
    if (warp >= NQ) return;

    float4 qv = *(const float4*)(g_qn + (size_t)warp * D + lane * 4);

    float v0 = -2.f, v1 = -2.f, v2 = -2.f;
    int   i0 = 0x7fffffff, i1 = 0x7fffffff, i2 = 0x7fffffff;

    size_t cb = (size_t)warp * NCH * KC;
    for (int j = 0; j < NCH * KC; ++j) {
        int gi = g_ci[cb + j];
        if ((unsigned)gi >= (unsigned)NM) continue;
        float4 mv = *(const float4*)(mem + (size_t)gi * D + lane * 4);
        float s = qv.x*mv.x + qv.y*mv.y + qv.z*mv.z + qv.w*mv.w;
        #pragma unroll
        for (int o = 16; o; o >>= 1) s += __shfl_xor_sync(0xffffffffu, s, o);
        s *= g_invm[gi];
        ins_tb3(s, gi, v0, i0, v1, i1, v2, i2);
    }
    if (lane == 0) {
        out[(size_t)warp * 3 + 0] = 1.0f - v0;
        out[(size_t)warp * 3 + 1] = 1.0f - v1;
        out[(size_t)warp * 3 + 2] = 1.0f - v2;
        out[(size_t)NQ * 3 + (size_t)warp * 3 + 0] = (float)i0;
        out[(size_t)NQ * 3 + (size_t)warp * 3 + 1] = (float)i1;
        out[(size_t)NQ * 3 + (size_t)warp * 3 + 2] = (float)i2;
    }
}

// ---------------- launch ----------------
extern "C" void kernel_launch(void* const* d_in, const int* in_sizes, int n_in,
                              void* d_out, int out_size) {
    const float* q   = (const float*)d_in[0];
    const float* mem = (const float*)d_in[1];
    float* out = (float*)d_out;

    cudaFuncSetAttribute(mma_topk_kernel,
                         cudaFuncAttributeMaxDynamicSharedMemorySize, SMEM_DYN);

    norm_q_kernel<<<(NQ * 32) / 256, 256>>>(q);
    norm_m_kernel<<<(NM * 32 + 255) / 256, 256>>>(mem);

    dim3 grid(NQ / QT, NCH);
    mma_topk_kernel<<<grid, 256, SMEM_DYN>>>();

    rescore_kernel<<<(NQ * 32) / 256, 256>>>(mem, out);
}

// round 4
// speedup vs baseline: 3.0506x; 1.1368x over previous
#include <cuda_runtime.h>
#include <cuda_bf16.h>
#include <cstdint>
#include <math.h>

// ---------------- problem constants ----------------
#define NQ     4096
#define NM     100000
#define D      128
#define NCH    37
#define CHUNK  2703          // ceil(NM / NCH)
#define QT     128           // queries per CTA (block M)
#define NT     256           // memory rows per tile (block N)
#define KC     4             // candidates kept per (query, chunk)

#define A_BYTES   (QT * D * 2)          // 32768
#define B_BYTES   (NT * D * 2)          // 65536
#define SMEM_DYN  (A_BYTES + 2 * B_BYTES + 1024)   // 164864

// ---------------- device scratch ----------------
__device__ float          g_qn[NQ * D];       // normalized queries (fp32)
__device__ __nv_bfloat16  g_qbf[NQ * D];      // normalized queries (bf16)
__device__ __nv_bfloat16  g_mbf[NM * D];      // normalized memory (bf16)
__device__ float          g_invm[NM];         // 1/||m||
__device__ float          g_cv[NQ * NCH * KC];
__device__ int            g_ci[NQ * NCH * KC];

// ---------------- PTX helpers (family-generic, sm_80-era) ----------------
__device__ __forceinline__ uint32_t s2u(const void* p) {
    uint32_t a;
    asm("{ .reg .u64 t; cvta.to.shared.u64 t, %1; cvt.u32.u64 %0, t; }"
        : "=r"(a) : "l"(p));
    return a;
}

__device__ __forceinline__ void cp16(uint32_t dst, const void* src) {
    asm volatile("cp.async.cg.shared.global [%0], [%1], 16;" :: "r"(dst), "l"(src));
}
#define CP_COMMIT() asm volatile("cp.async.commit_group;" ::: "memory")
#define CP_WAIT0()  asm volatile("cp.async.wait_group 0;" ::: "memory")

__device__ __forceinline__ void ldsm_x4(uint32_t addr, uint32_t& r0, uint32_t& r1,
                                        uint32_t& r2, uint32_t& r3) {
    asm volatile("ldmatrix.sync.aligned.m8n8.x4.shared.b16 {%0,%1,%2,%3}, [%4];"
        : "=r"(r0), "=r"(r1), "=r"(r2), "=r"(r3) : "r"(addr));
}

__device__ __forceinline__ void mma16816(float* d, const uint32_t* a, const uint32_t* b) {
    asm volatile("mma.sync.aligned.m16n8k16.row.col.f32.bf16.bf16.f32 "
        "{%0,%1,%2,%3}, {%4,%5,%6,%7}, {%8,%9}, {%0,%1,%2,%3};"
        : "+f"(d[0]), "+f"(d[1]), "+f"(d[2]), "+f"(d[3])
        : "r"(a[0]), "r"(a[1]), "r"(a[2]), "r"(a[3]), "r"(b[0]), "r"(b[1]));
}

// swizzled byte offset: row-major [row][128 bf16], 16B chunks XOR-permuted per row
__device__ __forceinline__ uint32_t sw_off(int row, int c16) {
    return (uint32_t)row * 256u + (uint32_t)((c16 ^ (row & 7)) * 16);
}

// ---------------- top-k inserts ----------------
__device__ __forceinline__ void ins_tb4(float s, int gi,
    float& v0, int& i0, float& v1, int& i1, float& v2, int& i2, float& v3, int& i3) {
    bool b3 = (s > v3) || (s == v3 && gi < i3);
    if (!b3) return;
    bool b1 = (s > v1) || (s == v1 && gi < i1);
    if (b1) {
        bool b0 = (s > v0) || (s == v0 && gi < i0);
        if (b0) { v3=v2;i3=i2; v2=v1;i2=i1; v1=v0;i1=i0; v0=s;i0=gi; }
        else    { v3=v2;i3=i2; v2=v1;i2=i1; v1=s;i1=gi; }
    } else {
        bool b2 = (s > v2) || (s == v2 && gi < i2);
        if (b2) { v3=v2;i3=i2; v2=s;i2=gi; }
        else    { v3=s; i3=gi; }
    }
}

__device__ __forceinline__ void ins_tb3(float s, int gi,
    float& v0, int& i0, float& v1, int& i1, float& v2, int& i2) {
    bool b2 = (s > v2) || (s == v2 && gi < i2);
    if (!b2) return;
    bool b1 = (s > v1) || (s == v1 && gi < i1);
    if (b1) {
        bool b0 = (s > v0) || (s == v0 && gi < i0);
        if (b0) { v2=v1;i2=i1; v1=v0;i1=i0; v0=s;i0=gi; }
        else    { v2=v1;i2=i1; v1=s;i1=gi; }
    } else      { v2=s; i2=gi; }
}

// ---------------- fused prep kernel (normalize q + m, emit bf16) ----------------
__global__ void prep_kernel(const float* __restrict__ q, const float* __restrict__ m) {
    int w    = (blockIdx.x * blockDim.x + threadIdx.x) >> 5;
    int lane = threadIdx.x & 31;
    if (w < NQ) {
        float4 v = *(const float4*)(q + (size_t)w * D + lane * 4);
        float ss = v.x*v.x + v.y*v.y + v.z*v.z + v.w*v.w;
        #pragma unroll
        for (int o = 16; o; o >>= 1) ss += __shfl_xor_sync(0xffffffffu, ss, o);
        float inv = 1.0f / fmaxf(sqrtf(ss), 1e-12f);
        float4 r = { v.x*inv, v.y*inv, v.z*inv, v.w*inv };
        *(float4*)(g_qn + (size_t)w * D + lane * 4) = r;
        __nv_bfloat162 p0 = __floats2bfloat162_rn(r.x, r.y);
        __nv_bfloat162 p1 = __floats2bfloat162_rn(r.z, r.w);
        *(__nv_bfloat162*)(g_qbf + (size_t)w * D + lane * 4)     = p0;
        *(__nv_bfloat162*)(g_qbf + (size_t)w * D + lane * 4 + 2) = p1;
    } else if (w < NQ + NM) {
        int row = w - NQ;
        float4 v = *(const float4*)(m + (size_t)row * D + lane * 4);
        float ss = v.x*v.x + v.y*v.y + v.z*v.z + v.w*v.w;
        #pragma unroll
        for (int o = 16; o; o >>= 1) ss += __shfl_xor_sync(0xffffffffu, ss, o);
        float inv = 1.0f / fmaxf(sqrtf(ss), 1e-12f);
        if (lane == 0) g_invm[row] = inv;
        __nv_bfloat162 p0 = __floats2bfloat162_rn(v.x*inv, v.y*inv);
        __nv_bfloat162 p1 = __floats2bfloat162_rn(v.z*inv, v.w*inv);
        *(__nv_bfloat162*)(g_mbf + (size_t)row * D + lane * 4)     = p0;
        *(__nv_bfloat162*)(g_mbf + (size_t)row * D + lane * 4 + 2) = p1;
    }
}

// ---------------- main HMMA + top-4 kernel ----------------
// 512 threads = 16 warps laid out 4(M) x 4(N). Block tile 128x256, K=128.
__global__ __launch_bounds__(512, 1) void mma_topk_kernel() {
    extern __shared__ __align__(16) uint8_t dyn[];

    int tid  = threadIdx.x;
    int wid  = tid >> 5;
    int lane = tid & 31;
    int wm   = wid & 3;       // warp row: 32 queries
    int wn   = wid >> 2;      // warp col: 64 memory rows (0..3)

    // align dynamic smem to 1024
    uint32_t raw  = s2u(dyn);
    uint32_t base = (raw + 1023u) & ~1023u;
    uint32_t aSm  = base;
    uint32_t bSm  = base + A_BYTES;

    int qbase  = blockIdx.x * QT;
    int chunk  = blockIdx.y;
    int mstart = chunk * CHUNK;
    int mend   = min(mstart + CHUNK, NM);
    int T      = (mend - mstart + NT - 1) / NT;

    // ---- prologue: A tile + B tile 0 via cp.async ----
    {
        int rowA = tid >> 2;                 // 128 rows, 4 threads/row
        int c16a = (tid & 3) * 4;
        #pragma unroll
        for (int j = 0; j < 4; ++j) {
            int c16 = c16a + j;
            cp16(aSm + sw_off(rowA, c16), g_qbf + (size_t)(qbase + rowA) * D + c16 * 8);
        }
        int rowB = tid >> 1;                 // 256 rows, 2 threads/row
        int c16b = (tid & 1) * 8;
        int gr = min(mstart + rowB, NM - 1);
        #pragma unroll
        for (int j = 0; j < 8; ++j) {
            int c16 = c16b + j;
            cp16(bSm + sw_off(rowB, c16), g_mbf + (size_t)gr * D + c16 * 8);
        }
    }
    CP_COMMIT();
    CP_WAIT0();
    __syncthreads();

    // per-thread top-4 for 4 row-slots (rs = mt*2 + half)
    float tv0[4], tv1[4], tv2[4], tv3[4];
    int   ti0[4], ti1[4], ti2[4], ti3[4];
    #pragma unroll
    for (int r = 0; r < 4; ++r) {
        tv0[r]=tv1[r]=tv2[r]=tv3[r] = -2.0f;
        ti0[r]=ti1[r]=ti2[r]=ti3[r] = 0x7fffffff;
    }

    int rowA0 = wm * 32 + (lane & 15);
    int hiA   = lane >> 4;
    int grp   = lane >> 3;
    int rowB0 = wn * 64 + (lane & 7) + (grp >> 1) * 8;
    int hiB   = grp & 1;

    for (int t = 0; t < T; ++t) {
        bool hn = (t + 1 < T);
        if (hn) {
            uint32_t bNext = bSm + ((t + 1) & 1) * B_BYTES;
            int rowB = tid >> 1;
            int c16b = (tid & 1) * 8;
            int gr = min(mstart + (t + 1) * NT + rowB, NM - 1);
            #pragma unroll
            for (int j = 0; j < 8; ++j) {
                int c16 = c16b + j;
                cp16(bNext + sw_off(rowB, c16), g_mbf + (size_t)gr * D + c16 * 8);
            }
            CP_COMMIT();
        }

        uint32_t bB = bSm + (t & 1) * B_BYTES;
        int tb = mstart + t * NT;

        // ---- 128x256x128 block tile ----
        float acc[2][8][4];
        #pragma unroll
        for (int mt = 0; mt < 2; ++mt)
            #pragma unroll
            for (int nt = 0; nt < 8; ++nt)
                #pragma unroll
                for (int e = 0; e < 4; ++e) acc[mt][nt][e] = 0.0f;

        #pragma unroll
        for (int kk = 0; kk < 8; ++kk) {
            uint32_t a[2][4];
            #pragma unroll
            for (int mt = 0; mt < 2; ++mt) {
                int row = rowA0 + mt * 16;
                ldsm_x4(aSm + sw_off(row, 2 * kk + hiA),
                        a[mt][0], a[mt][1], a[mt][2], a[mt][3]);
            }
            uint32_t b[8][2];
            #pragma unroll
            for (int j = 0; j < 4; ++j) {
                int row = rowB0 + j * 16;
                ldsm_x4(bB + sw_off(row, 2 * kk + hiB),
                        b[2*j][0], b[2*j][1], b[2*j+1][0], b[2*j+1][1]);
            }
            #pragma unroll
            for (int mt = 0; mt < 2; ++mt)
                #pragma unroll
                for (int nt = 0; nt < 8; ++nt)
                    mma16816(acc[mt][nt], a[mt], b[nt]);
        }

        // ---- streaming top-4 epilogue ----
        #pragma unroll
        for (int mt = 0; mt < 2; ++mt)
            #pragma unroll
            for (int h = 0; h < 2; ++h) {
                const int rs = mt * 2 + h;
                #pragma unroll
                for (int nt = 0; nt < 8; ++nt)
                    #pragma unroll
                    for (int c = 0; c < 2; ++c) {
                        float s = acc[mt][nt][h * 2 + c];
                        int gi = tb + wn * 64 + nt * 8 + (lane & 3) * 2 + c;
                        if (gi < mend && s > tv3[rs]) {
                            if (s > tv1[rs]) {
                                if (s > tv0[rs]) {
                                    tv3[rs]=tv2[rs];ti3[rs]=ti2[rs];
                                    tv2[rs]=tv1[rs];ti2[rs]=ti1[rs];
                                    tv1[rs]=tv0[rs];ti1[rs]=ti0[rs];
                                    tv0[rs]=s;      ti0[rs]=gi;
                                } else {
                                    tv3[rs]=tv2[rs];ti3[rs]=ti2[rs];
                                    tv2[rs]=tv1[rs];ti2[rs]=ti1[rs];
                                    tv1[rs]=s;      ti1[rs]=gi;
                                }
                            } else {
                                if (s > tv2[rs]) {
                                    tv3[rs]=tv2[rs];ti3[rs]=ti2[rs];
                                    tv2[rs]=s;      ti2[rs]=gi;
                                } else { tv3[rs]=s; ti3[rs]=gi; }
                            }
                        }
                    }
            }

        if (hn) CP_WAIT0();
        __syncthreads();
    }

    // ---- merge across the 4 lanes sharing each row (xor 1, 2) ----
    #pragma unroll
    for (int off = 1; off <= 2; off <<= 1) {
        #pragma unroll
        for (int rs = 0; rs < 4; ++rs) {
            float ov0 = __shfl_xor_sync(0xffffffffu, tv0[rs], off);
            int   oi0 = __shfl_xor_sync(0xffffffffu, ti0[rs], off);
            float ov1 = __shfl_xor_sync(0xffffffffu, tv1[rs], off);
            int   oi1 = __shfl_xor_sync(0xffffffffu, ti1[rs], off);
            float ov2 = __shfl_xor_sync(0xffffffffu, tv2[rs], off);
            int   oi2 = __shfl_xor_sync(0xffffffffu, ti2[rs], off);
            float ov3 = __shfl_xor_sync(0xffffffffu, tv3[rs], off);
            int   oi3 = __shfl_xor_sync(0xffffffffu, ti3[rs], off);
            ins_tb4(ov0, oi0, tv0[rs],ti0[rs], tv1[rs],ti1[rs], tv2[rs],ti2[rs], tv3[rs],ti3[rs]);
            ins_tb4(ov1, oi1, tv0[rs],ti0[rs], tv1[rs],ti1[rs], tv2[rs],ti2[rs], tv3[rs],ti3[rs]);
            ins_tb4(ov2, oi2, tv0[rs],ti0[rs], tv1[rs],ti1[rs], tv2[rs],ti2[rs], tv3[rs],ti3[rs]);
            ins_tb4(ov3, oi3, tv0[rs],ti0[rs], tv1[rs],ti1[rs], tv2[rs],ti2[rs], tv3[rs],ti3[rs]);
        }
    }
    __syncthreads();   // all cp.async drained; smem reusable

    // ---- cross-warp_n merge via smem: [4 warp-cols][128 rows][4 slots] ----
    float* smv = (float*)dyn;                         // 8 KB
    int*   smi = (int*)(dyn + 4 * 128 * 4 * 4);       // 8 KB
    if ((lane & 3) == 0) {
        #pragma unroll
        for (int rs = 0; rs < 4; ++rs) {
            int row = wm * 32 + (rs >> 1) * 16 + (lane >> 2) + (rs & 1) * 8;
            int o = (wn * 128 + row) * 4;
            smv[o+0]=tv0[rs]; smi[o+0]=ti0[rs];
            smv[o+1]=tv1[rs]; smi[o+1]=ti1[rs];
            smv[o+2]=tv2[rs]; smi[o+2]=ti2[rs];
            smv[o+3]=tv3[rs]; smi[o+3]=ti3[rs];
        }
    }
    __syncthreads();
    if (tid < 128) {
        int row = tid;
        int o0 = row * 4;
        float v0 = smv[o0+0], v1 = smv[o0+1], v2 = smv[o0+2], v3 = smv[o0+3];
        int   i0 = smi[o0+0], i1 = smi[o0+1], i2 = smi[o0+2], i3 = smi[o0+3];
        #pragma unroll
        for (int seg = 1; seg < 4; ++seg) {
            int o1 = (seg * 128 + row) * 4;
            #pragma unroll
            for (int j = 0; j < 4; ++j)
                ins_tb4(smv[o1+j], smi[o1+j], v0,i0, v1,i1, v2,i2, v3,i3);
        }
        size_t cb = ((size_t)(qbase + row) * NCH + chunk) * KC;
        g_cv[cb+0]=v0; g_ci[cb+0]=i0;
        g_cv[cb+1]=v1; g_ci[cb+1]=i1;
        g_cv[cb+2]=v2; g_ci[cb+2]=i2;
        g_cv[cb+3]=v3; g_ci[cb+3]=i3;
    }
}

// ---------------- exact fp32 rescore + final top-3 ----------------
// Block = 256 threads = 2 queries x 4 warps. Each warp rescans 37 candidates,
// partial top-3s merged in smem with exact tie-break ordering.
__global__ void rescore_kernel(const float* __restrict__ mem, float* __restrict__ out) {
    __shared__ float sv[2][4][3];
    __shared__ int   si[2][4][3];

    int tid   = threadIdx.x;
    int wid   = tid >> 5;
    int lane  = tid & 31;
    int qloc  = wid >> 2;                 // 0..1
    int part  = wid & 3;                  // 0..3
    int qidx  = blockIdx.x * 2 + qloc;

    float4 qv = *(const float4*)(g_qn + (size_t)qidx * D + lane * 4);

    float v0 = -2.f, v1 = -2.f, v2 = -2.f;
    int   i0 = 0x7fffffff, i1 = 0x7fffffff, i2 = 0x7fffffff;

    size_t cb = (size_t)qidx * NCH * KC + (size_t)part * NCH;
    #pragma unroll 1
    for (int j = 0; j < NCH; ++j) {
        int gi = g_ci[cb + j];
        if ((unsigned)gi >= (unsigned)NM) continue;
        float4 mv = *(const float4*)(mem + (size_t)gi * D + lane * 4);
        float s = qv.x*mv.x + qv.y*mv.y + qv.z*mv.z + qv.w*mv.w;
        #pragma unroll
        for (int o = 16; o; o >>= 1) s += __shfl_xor_sync(0xffffffffu, s, o);
        s *= g_invm[gi];
        ins_tb3(s, gi, v0, i0, v1, i1, v2, i2);
    }
    if (lane == 0) {
        sv[qloc][part][0]=v0; si[qloc][part][0]=i0;
        sv[qloc][part][1]=v1; si[qloc][part][1]=i1;
        sv[qloc][part][2]=v2; si[qloc][part][2]=i2;
    }
    __syncthreads();

    if (part == 0 && lane == 0) {
        float w0 = -2.f, w1 = -2.f, w2 = -2.f;
        int   a0 = 0x7fffffff, a1 = 0x7fffffff, a2 = 0x7fffffff;
        #pragma unroll
        for (int p = 0; p < 4; ++p)
            #pragma unroll
            for (int j = 0; j < 3; ++j)
                ins_tb3(sv[qloc][p][j], si[qloc][p][j], w0,a0, w1,a1, w2,a2);
        out[(size_t)qidx * 3 + 0] = 1.0f - w0;
        out[(size_t)qidx * 3 + 1] = 1.0f - w1;
        out[(size_t)qidx * 3 + 2] = 1.0f - w2;
        out[(size_t)NQ * 3 + (size_t)qidx * 3 + 0] = (float)a0;
        out[(size_t)NQ * 3 + (size_t)qidx * 3 + 1] = (float)a1;
        out[(size_t)NQ * 3 + (size_t)qidx * 3 + 2] = (float)a2;
    }
}

// ---------------- launch ----------------
extern "C" void kernel_launch(void* const* d_in, const int* in_sizes, int n_in,
                              void* d_out, int out_size) {
    const float* q   = (const float*)d_in[0];
    const float* mem = (const float*)d_in[1];
    float* out = (float*)d_out;

    cudaFuncSetAttribute(mma_topk_kernel,
                         cudaFuncAttributeMaxDynamicSharedMemorySize, SMEM_DYN);

    int prep_warps = NQ + NM;
    prep_kernel<<<(prep_warps * 32 + 255) / 256, 256>>>(q, mem);

    dim3 grid(NQ / QT, NCH);
    mma_topk_kernel<<<grid, 512, SMEM_DYN>>>();

    rescore_kernel<<<NQ / 2, 256>>>(mem, out);
}

// round 5
// speedup vs baseline: 3.3695x; 1.1045x over previous
#include <cuda_runtime.h>
#include <cuda_bf16.h>
#include <cuda_fp8.h>
#include <cstdint>
#include <math.h>

// ---------------- problem constants ----------------
#define NQ     4096
#define NM     100000
#define D      128
#define NCH    37
#define CHUNK  2703          // ceil(NM / NCH)
#define QT     128           // queries per CTA (block M)
#define NT     128           // memory rows per tile (block N)
#define KC     8             // candidates kept per (query, chunk)

#define A_BYTES   (QT * D)              // fp8: 16384
#define B_BYTES   (NT * D)              // 16384
#define SMEM_DYN  (A_BYTES + 2 * B_BYTES + 1024)   // ~50KB

// ---------------- device scratch ----------------
__device__ float     g_qn[NQ * D];        // normalized queries (fp32)
__device__ uint32_t  g_qf8[NQ * 32];      // normalized queries (e4m3, 4/word)
__device__ uint32_t  g_mf8[NM * 32];      // normalized memory (e4m3)
__device__ float     g_invm[NM];          // 1/||m||
__device__ float     g_cv[NQ * NCH * KC];
__device__ int       g_ci[NQ * NCH * KC];

// ---------------- PTX helpers (family-generic, sm_89-era max) ----------------
__device__ __forceinline__ uint32_t s2u(const void* p) {
    uint32_t a;
    asm("{ .reg .u64 t; cvta.to.shared.u64 t, %1; cvt.u32.u64 %0, t; }"
        : "=r"(a) : "l"(p));
    return a;
}

__device__ __forceinline__ void cp16(uint32_t dst, const void* src) {
    asm volatile("cp.async.cg.shared.global [%0], [%1], 16;" :: "r"(dst), "l"(src));
}
#define CP_COMMIT() asm volatile("cp.async.commit_group;" ::: "memory")
#define CP_WAIT0()  asm volatile("cp.async.wait_group 0;" ::: "memory")

__device__ __forceinline__ void ldsm_x4(uint32_t addr, uint32_t& r0, uint32_t& r1,
                                        uint32_t& r2, uint32_t& r3) {
    asm volatile("ldmatrix.sync.aligned.m8n8.x4.shared.b16 {%0,%1,%2,%3}, [%4];"
        : "=r"(r0), "=r"(r1), "=r"(r2), "=r"(r3) : "r"(addr));
}

// fp8 e4m3 MMA: m16n8k32, fragments byte-identical to bf16 m16n8k16 pattern
__device__ __forceinline__ void mma16832(float* d, const uint32_t* a, const uint32_t* b) {
    asm volatile("mma.sync.aligned.m16n8k32.row.col.f32.e4m3.e4m3.f32 "
        "{%0,%1,%2,%3}, {%4,%5,%6,%7}, {%8,%9}, {%0,%1,%2,%3};"
        : "+f"(d[0]), "+f"(d[1]), "+f"(d[2]), "+f"(d[3])
        : "r"(a[0]), "r"(a[1]), "r"(a[2]), "r"(a[3]), "r"(b[0]), "r"(b[1]));
}

// swizzled byte offset: rows of 128 bytes, 16B chunks XOR-permuted per row
__device__ __forceinline__ uint32_t sw_off(int row, int c16) {
    return (uint32_t)row * 128u + (uint32_t)((c16 ^ (row & 7)) * 16);
}

// ---------------- top-k inserts ----------------
__device__ __forceinline__ void ins_tb3(float s, int gi,
    float& v0, int& i0, float& v1, int& i1, float& v2, int& i2) {
    bool b2 = (s > v2) || (s == v2 && gi < i2);
    if (!b2) return;
    bool b1 = (s > v1) || (s == v1 && gi < i1);
    if (b1) {
        bool b0 = (s > v0) || (s == v0 && gi < i0);
        if (b0) { v2=v1;i2=i1; v1=v0;i1=i0; v0=s;i0=gi; }
        else    { v2=v1;i2=i1; v1=s;i1=gi; }
    } else      { v2=s; i2=gi; }
}

__device__ __forceinline__ void ins_tb4(float s, int gi,
    float& v0, int& i0, float& v1, int& i1, float& v2, int& i2, float& v3, int& i3) {
    bool b3 = (s > v3);
    if (!b3) return;
    if (s > v1) {
        if (s > v0) { v3=v2;i3=i2; v2=v1;i2=i1; v1=v0;i1=i0; v0=s;i0=gi; }
        else        { v3=v2;i3=i2; v2=v1;i2=i1; v1=s;i1=gi; }
    } else {
        if (s > v2) { v3=v2;i3=i2; v2=s;i2=gi; }
        else        { v3=s; i3=gi; }
    }
}

// ---------------- fused prep kernel (normalize q + m, emit fp8) ----------------
__global__ void prep_kernel(const float* __restrict__ q, const float* __restrict__ m) {
    int w    = (blockIdx.x * blockDim.x + threadIdx.x) >> 5;
    int lane = threadIdx.x & 31;
    if (w < NQ) {
        float4 v = *(const float4*)(q + (size_t)w * D + lane * 4);
        float ss = v.x*v.x + v.y*v.y + v.z*v.z + v.w*v.w;
        #pragma unroll
        for (int o = 16; o; o >>= 1) ss += __shfl_xor_sync(0xffffffffu, ss, o);
        float inv = 1.0f / fmaxf(sqrtf(ss), 1e-12f);
        float4 r = { v.x*inv, v.y*inv, v.z*inv, v.w*inv };
        *(float4*)(g_qn + (size_t)w * D + lane * 4) = r;
        uint32_t lo = __nv_cvt_float2_to_fp8x2(make_float2(r.x, r.y), __NV_SATFINITE, __NV_E4M3);
        uint32_t hi = __nv_cvt_float2_to_fp8x2(make_float2(r.z, r.w), __NV_SATFINITE, __NV_E4M3);
        g_qf8[(size_t)w * 32 + lane] = (lo & 0xffffu) | (hi << 16);
    } else if (w < NQ + NM) {
        int row = w - NQ;
        float4 v = *(const float4*)(m + (size_t)row * D + lane * 4);
        float ss = v.x*v.x + v.y*v.y + v.z*v.z + v.w*v.w;
        #pragma unroll
        for (int o = 16; o; o >>= 1) ss += __shfl_xor_sync(0xffffffffu, ss, o);
        float inv = 1.0f / fmaxf(sqrtf(ss), 1e-12f);
        if (lane == 0) g_invm[row] = inv;
        float2 a = make_float2(v.x*inv, v.y*inv);
        float2 b = make_float2(v.z*inv, v.w*inv);
        uint32_t lo = __nv_cvt_float2_to_fp8x2(a, __NV_SATFINITE, __NV_E4M3);
        uint32_t hi = __nv_cvt_float2_to_fp8x2(b, __NV_SATFINITE, __NV_E4M3);
        g_mf8[(size_t)row * 32 + lane] = (lo & 0xffffu) | (hi << 16);
    }
}

// ---------------- main FP8 MMA + top-8 kernel ----------------
// 512 threads = 16 warps laid out 4(M) x 4(N). Block tile 128x128, K=128.
// Warp tile 32x32 -> only 32 accumulator regs (no spills).
__global__ __launch_bounds__(512, 1) void mma_topk_kernel() {
    extern __shared__ __align__(16) uint8_t dyn[];

    int tid  = threadIdx.x;
    int wid  = tid >> 5;
    int lane = tid & 31;
    int wm   = wid & 3;       // warp row: 32 queries
    int wn   = wid >> 2;      // warp col: 32 memory rows (0..3)

    uint32_t raw  = s2u(dyn);
    uint32_t base = (raw + 1023u) & ~1023u;
    uint8_t* dbase = (uint8_t*)dyn + (base - raw);
    uint32_t aSm  = base;
    uint32_t bSm  = base + A_BYTES;

    int qbase  = blockIdx.x * QT;
    int chunk  = blockIdx.y;
    int mstart = chunk * CHUNK;
    int mend   = min(mstart + CHUNK, NM);
    int T      = (mend - mstart + NT - 1) / NT;

    const char* mf8 = (const char*)g_mf8;
    const char* qf8 = (const char*)g_qf8;

    // ---- prologue: A tile + B tile 0 via cp.async (32B per thread each) ----
    {
        int row = tid >> 2;                  // 128 rows, 4 threads/row
        int c16a = (tid & 3) * 2;
        #pragma unroll
        for (int j = 0; j < 2; ++j)
            cp16(aSm + sw_off(row, c16a + j), qf8 + (size_t)(qbase + row) * 128 + (c16a + j) * 16);
        int gr = min(mstart + row, NM - 1);
        #pragma unroll
        for (int j = 0; j < 2; ++j)
            cp16(bSm + sw_off(row, c16a + j), mf8 + (size_t)gr * 128 + (c16a + j) * 16);
    }
    CP_COMMIT();
    CP_WAIT0();
    __syncthreads();

    // per-thread top-4 for 4 row-slots (rs = mt*2 + h)
    float tv0[4], tv1[4], tv2[4], tv3[4];
    int   ti0[4], ti1[4], ti2[4], ti3[4];
    #pragma unroll
    for (int r = 0; r < 4; ++r) {
        tv0[r]=tv1[r]=tv2[r]=tv3[r] = -2.0f;
        ti0[r]=ti1[r]=ti2[r]=ti3[r] = 0x7fffffff;
    }

    int rowA0 = wm * 32 + (lane & 15);
    int hiA   = lane >> 4;
    int grp   = lane >> 3;
    int rowB0 = wn * 32 + (lane & 7) + (grp >> 1) * 8;
    int hiB   = grp & 1;

    for (int t = 0; t < T; ++t) {
        bool hn = (t + 1 < T);
        if (hn) {
            uint32_t bNext = bSm + ((t + 1) & 1) * B_BYTES;
            int row = tid >> 2;
            int c16b = (tid & 3) * 2;
            int gr = min(mstart + (t + 1) * NT + row, NM - 1);
            #pragma unroll
            for (int j = 0; j < 2; ++j)
                cp16(bNext + sw_off(row, c16b + j), mf8 + (size_t)gr * 128 + (c16b + j) * 16);
            CP_COMMIT();
        }

        uint32_t bB = bSm + (t & 1) * B_BYTES;
        int tb = mstart + t * NT;

        // ---- 128x128x128 block tile, fp8 (4 K-steps of 32) ----
        float acc[2][4][4];
        #pragma unroll
        for (int mt = 0; mt < 2; ++mt)
            #pragma unroll
            for (int nt = 0; nt < 4; ++nt)
                #pragma unroll
                for (int e = 0; e < 4; ++e) acc[mt][nt][e] = 0.0f;

        #pragma unroll
        for (int kk = 0; kk < 4; ++kk) {
            uint32_t a[2][4];
            #pragma unroll
            for (int mt = 0; mt < 2; ++mt)
                ldsm_x4(aSm + sw_off(rowA0 + mt * 16, 2 * kk + hiA),
                        a[mt][0], a[mt][1], a[mt][2], a[mt][3]);
            uint32_t b[4][2];
            #pragma unroll
            for (int j = 0; j < 2; ++j)
                ldsm_x4(bB + sw_off(rowB0 + j * 16, 2 * kk + hiB),
                        b[2*j][0], b[2*j][1], b[2*j+1][0], b[2*j+1][1]);
            #pragma unroll
            for (int mt = 0; mt < 2; ++mt)
                #pragma unroll
                for (int nt = 0; nt < 4; ++nt)
                    mma16832(acc[mt][nt], a[mt], b[nt]);
        }

        // ---- streaming top-4 epilogue (gi ascending per row-slot) ----
        #pragma unroll
        for (int mt = 0; mt < 2; ++mt)
            #pragma unroll
            for (int h = 0; h < 2; ++h) {
                const int rs = mt * 2 + h;
                #pragma unroll
                for (int nt = 0; nt < 4; ++nt)
                    #pragma unroll
                    for (int c = 0; c < 2; ++c) {
                        float s = acc[mt][nt][h * 2 + c];
                        int gi = tb + wn * 32 + nt * 8 + (lane & 3) * 2 + c;
                        if (gi < mend && s > tv3[rs])
                            ins_tb4(s, gi, tv0[rs],ti0[rs], tv1[rs],ti1[rs],
                                           tv2[rs],ti2[rs], tv3[rs],ti3[rs]);
                    }
            }

        if (hn) CP_WAIT0();
        __syncthreads();
    }

    // ---- merge across the 4 lanes sharing each row (xor 1, 2) ----
    #pragma unroll
    for (int off = 1; off <= 2; off <<= 1) {
        #pragma unroll
        for (int rs = 0; rs < 4; ++rs) {
            float ov0 = __shfl_xor_sync(0xffffffffu, tv0[rs], off);
            int   oi0 = __shfl_xor_sync(0xffffffffu, ti0[rs], off);
            float ov1 = __shfl_xor_sync(0xffffffffu, tv1[rs], off);
            int   oi1 = __shfl_xor_sync(0xffffffffu, ti1[rs], off);
            float ov2 = __shfl_xor_sync(0xffffffffu, tv2[rs], off);
            int   oi2 = __shfl_xor_sync(0xffffffffu, ti2[rs], off);
            float ov3 = __shfl_xor_sync(0xffffffffu, tv3[rs], off);
            int   oi3 = __shfl_xor_sync(0xffffffffu, ti3[rs], off);
            ins_tb4(ov0, oi0, tv0[rs],ti0[rs], tv1[rs],ti1[rs], tv2[rs],ti2[rs], tv3[rs],ti3[rs]);
            ins_tb4(ov1, oi1, tv0[rs],ti0[rs], tv1[rs],ti1[rs], tv2[rs],ti2[rs], tv3[rs],ti3[rs]);
            ins_tb4(ov2, oi2, tv0[rs],ti0[rs], tv1[rs],ti1[rs], tv2[rs],ti2[rs], tv3[rs],ti3[rs]);
            ins_tb4(ov3, oi3, tv0[rs],ti0[rs], tv1[rs],ti1[rs], tv2[rs],ti2[rs], tv3[rs],ti3[rs]);
        }
    }
    __syncthreads();   // all cp.async drained; smem reusable

    // ---- cross-warp_n merge via smem: [4 wn][128 rows][4 slots] ----
    float* smv = (float*)dbase;                         // 8 KB
    int*   smi = (int*)(dbase + 4 * 128 * 4 * 4);       // 8 KB
    if ((lane & 3) == 0) {
        #pragma unroll
        for (int rs = 0; rs < 4; ++rs) {
            int row = wm * 32 + (rs >> 1) * 16 + (lane >> 2) + (rs & 1) * 8;
            int o = (wn * 128 + row) * 4;
            smv[o+0]=tv0[rs]; smi[o+0]=ti0[rs];
            smv[o+1]=tv1[rs]; smi[o+1]=ti1[rs];
            smv[o+2]=tv2[rs]; smi[o+2]=ti2[rs];
            smv[o+3]=tv3[rs]; smi[o+3]=ti3[rs];
        }
    }
    __syncthreads();
    if (tid < 128) {
        int row = tid;
        float av[16]; int ai[16];
        #pragma unroll
        for (int seg = 0; seg < 4; ++seg)
            #pragma unroll
            for (int j = 0; j < 4; ++j) {
                av[seg*4+j] = smv[(seg * 128 + row) * 4 + j];
                ai[seg*4+j] = smi[(seg * 128 + row) * 4 + j];
            }
        // selection of top-8 (approximate values; ties arbitrary — rescore is exact)
        size_t cb = ((size_t)(qbase + row) * NCH + chunk) * KC;
        #pragma unroll
        for (int s = 0; s < KC; ++s) {
            int best = s;
            for (int j = s + 1; j < 16; ++j)
                if (av[j] > av[best]) best = j;
            float bv = av[best]; int bi = ai[best];
            av[best] = av[s]; ai[best] = ai[s];
            av[s] = bv; ai[s] = bi;
            g_cv[cb + s] = bv; g_ci[cb + s] = bi;
        }
    }
}

// ---------------- exact fp32 rescore + final top-3 ----------------
// Block = 256 threads = 8 warps, one query per block. Each warp rescans 37
// candidates; partial top-3s merged with exact jax tie-break ordering.
__global__ void rescore_kernel(const float* __restrict__ mem, float* __restrict__ out) {
    __shared__ float sv[8][3];
    __shared__ int   si[8][3];

    int tid   = threadIdx.x;
    int wid   = tid >> 5;
    int lane  = tid & 31;
    int qidx  = blockIdx.x;

    float4 qv = *(const float4*)(g_qn + (size_t)qidx * D + lane * 4);

    float v0 = -2.f, v1 = -2.f, v2 = -2.f;
    int   i0 = 0x7fffffff, i1 = 0x7fffffff, i2 = 0x7fffffff;

    size_t cb = (size_t)qidx * NCH * KC;
    #pragma unroll 1
    for (int j = wid; j < NCH * KC; j += 8) {
        int gi = g_ci[cb + j];
        if ((unsigned)gi >= (unsigned)NM) continue;
        float4 mv = *(const float4*)(mem + (size_t)gi * D + lane * 4);
        float s = qv.x*mv.x + qv.y*mv.y + qv.z*mv.z + qv.w*mv.w;
        #pragma unroll
        for (int o = 16; o; o >>= 1) s += __shfl_xor_sync(0xffffffffu, s, o);
        s *= g_invm[gi];
        ins_tb3(s, gi, v0, i0, v1, i1, v2, i2);
    }
    if (lane == 0) {
        sv[wid][0]=v0; si[wid][0]=i0;
        sv[wid][1]=v1; si[wid][1]=i1;
        sv[wid][2]=v2; si[wid][2]=i2;
    }
    __syncthreads();

    if (tid == 0) {
        float w0 = -2.f, w1 = -2.f, w2 = -2.f;
        int   a0 = 0x7fffffff, a1 = 0x7fffffff, a2 = 0x7fffffff;
        #pragma unroll
        for (int p = 0; p < 8; ++p)
            #pragma unroll
            for (int j = 0; j < 3; ++j)
                ins_tb3(sv[p][j], si[p][j], w0,a0, w1,a1, w2,a2);
        out[(size_t)qidx * 3 + 0] = 1.0f - w0;
        out[(size_t)qidx * 3 + 1] = 1.0f - w1;
        out[(size_t)qidx * 3 + 2] = 1.0f - w2;
        out[(size_t)NQ * 3 + (size_t)qidx * 3 + 0] = (float)a0;
        out[(size_t)NQ * 3 + (size_t)qidx * 3 + 1] = (float)a1;
        out[(size_t)NQ * 3 + (size_t)qidx * 3 + 2] = (float)a2;
    }
}

// ---------------- launch ----------------
extern "C" void kernel_launch(void* const* d_in, const int* in_sizes, int n_in,
                              void* d_out, int out_size) {
    const float* q   = (const float*)d_in[0];
    const float* mem = (const float*)d_in[1];
    float* out = (float*)d_out;

    cudaFuncSetAttribute(mma_topk_kernel,
                         cudaFuncAttributeMaxDynamicSharedMemorySize, SMEM_DYN);

    int prep_warps = NQ + NM;
    prep_kernel<<<(prep_warps * 32 + 255) / 256, 256>>>(q, mem);

    dim3 grid(NQ / QT, NCH);
    mma_topk_kernel<<<grid, 512, SMEM_DYN>>>();

    rescore_kernel<<<NQ, 256>>>(mem, out);
}